// round 5
// baseline (speedup 1.0000x reference)
#include <cuda_runtime.h>
#include <cstdint>
#include <math.h>

// Problem constants
static constexpr int S   = 1024;
static constexpr int H   = 2880;
static constexpr int NH  = 64;
static constexpr int NKV = 8;
static constexpr int HD  = 64;
static constexpr int QKV_N = (NH + 2 * NKV) * HD;   // 5120
static constexpr int OD    = NH * HD;               // 4096

// Scratch (allocation-free rule: __device__ globals)
__device__ __align__(16) float g_qkv [S * QKV_N];   // 20 MB
__device__ __align__(16) float g_attn[S * OD];      // 16 MB
__device__ __align__(16) float g_rope[S * 64];      // cos[32] | sin[32] per row

// ---------------------------------------------------------------------------
// TF32 tensor-core GEMM:  C[M,N] = A[M,K] @ B[N,K]^T   (unchanged from R4)
// ---------------------------------------------------------------------------
static constexpr int BM = 128, BN = 128, BK = 16;
static constexpr int SST = 20;                  // padded smem row stride (floats)

__device__ __forceinline__ uint32_t f2tf32(float f) {
    uint32_t r;
    asm volatile("cvt.rna.tf32.f32 %0, %1;" : "=r"(r) : "f"(f));
    return r;
}

__device__ __forceinline__ void cp16(float* s, const float* g, bool pred) {
    uint32_t sa = (uint32_t)__cvta_generic_to_shared(s);
    int sz = pred ? 16 : 0;
    asm volatile("cp.async.cg.shared.global [%0], [%1], 16, %2;"
                 :: "r"(sa), "l"(g), "r"(sz));
}

__global__ __launch_bounds__(256, 2) void gemm_tf32(
    const float* __restrict__ A, const float* __restrict__ B,
    float* __restrict__ C, int M, int N, int K)
{
    __shared__ float As[2][BM * SST];
    __shared__ float Bs[2][BN * SST];

    const int t    = threadIdx.x;
    const int lane = t & 31;
    const int warp = t >> 5;
    const int wRow = warp >> 1;
    const int wCol = warp & 1;
    const int bm   = blockIdx.y * BM;
    const int bn   = blockIdx.x * BN;

    const int gr = lane >> 2;
    const int kc = lane & 3;

    float acc[2][8][4];
#pragma unroll
    for (int i = 0; i < 2; ++i)
#pragma unroll
        for (int j = 0; j < 8; ++j)
#pragma unroll
            for (int r = 0; r < 4; ++r) acc[i][j][r] = 0.f;

    auto load_tile = [&](int buf, int kt) {
#pragma unroll
        for (int i = 0; i < 2; ++i) {
            const int ch  = t + 256 * i;
            const int row = ch >> 2;
            const int c4  = (ch & 3) << 2;
            cp16(&As[buf][row * SST + c4],
                 A + (size_t)(bm + row) * K + kt + c4, true);
            cp16(&Bs[buf][row * SST + c4],
                 B + (size_t)(bn + row) * K + kt + c4, (bn + row) < N);
        }
    };

    int buf = 0;
    load_tile(buf, 0);
    asm volatile("cp.async.commit_group;");

    for (int kt = 0; kt < K; kt += BK) {
        const int nxt = kt + BK;
        if (nxt < K) {
            load_tile(buf ^ 1, nxt);
            asm volatile("cp.async.commit_group;");
            asm volatile("cp.async.wait_group 1;");
        } else {
            asm volatile("cp.async.wait_group 0;");
        }
        __syncthreads();

        const float* as = As[buf];
        const float* bs = Bs[buf];
#pragma unroll
        for (int k8 = 0; k8 < BK; k8 += 8) {
            uint32_t af[2][4], bf[8][2];
#pragma unroll
            for (int i = 0; i < 2; ++i) {
                const int rb = wRow * 32 + i * 16;
                af[i][0] = f2tf32(as[(rb + gr)     * SST + k8 + kc]);
                af[i][1] = f2tf32(as[(rb + gr + 8) * SST + k8 + kc]);
                af[i][2] = f2tf32(as[(rb + gr)     * SST + k8 + kc + 4]);
                af[i][3] = f2tf32(as[(rb + gr + 8) * SST + k8 + kc + 4]);
            }
#pragma unroll
            for (int j = 0; j < 8; ++j) {
                const int cb = wCol * 64 + j * 8;
                bf[j][0] = f2tf32(bs[(cb + gr) * SST + k8 + kc]);
                bf[j][1] = f2tf32(bs[(cb + gr) * SST + k8 + kc + 4]);
            }
#pragma unroll
            for (int i = 0; i < 2; ++i)
#pragma unroll
                for (int j = 0; j < 8; ++j) {
                    asm volatile(
                        "mma.sync.aligned.m16n8k8.row.col.f32.tf32.tf32.f32 "
                        "{%0,%1,%2,%3}, {%4,%5,%6,%7}, {%8,%9}, {%0,%1,%2,%3};"
                        : "+f"(acc[i][j][0]), "+f"(acc[i][j][1]),
                          "+f"(acc[i][j][2]), "+f"(acc[i][j][3])
                        : "r"(af[i][0]), "r"(af[i][1]), "r"(af[i][2]), "r"(af[i][3]),
                          "r"(bf[j][0]), "r"(bf[j][1]));
                }
        }
        __syncthreads();
        buf ^= 1;
    }

#pragma unroll
    for (int i = 0; i < 2; ++i) {
        const int row = bm + wRow * 32 + i * 16 + gr;
#pragma unroll
        for (int j = 0; j < 8; ++j) {
            const int col = bn + wCol * 64 + j * 8 + kc * 2;
            if (col < N) {
                *(float2*)(C + (size_t)row * N + col) =
                    make_float2(acc[i][j][0], acc[i][j][1]);
                *(float2*)(C + (size_t)(row + 8) * N + col) =
                    make_float2(acc[i][j][2], acc[i][j][3]);
            }
        }
    }
}

// ---------------------------------------------------------------------------
// RoPE: precompute cos/sin table (double sincos, 32K threads), then apply.
// ---------------------------------------------------------------------------
__global__ void rope_table(const int* __restrict__ positions, float* __restrict__ tab)
{
    const int id = blockIdx.x * blockDim.x + threadIdx.x;
    if (id >= S * 32) return;
    const int p = id & 31;
    const int s = id >> 5;
    const float freq = 1.0f / powf(10000.0f, (float)p * (1.0f / 32.0f));
    const float ang  = (float)positions[s] * freq;
    double sd, cd;
    sincos((double)ang, &sd, &cd);
    tab[s * 64 + p]      = (float)cd;
    tab[s * 64 + 32 + p] = (float)sd;
}

__global__ void rope_apply(float* __restrict__ qkv, const float* __restrict__ tab)
{
    const int id = blockIdx.x * blockDim.x + threadIdx.x;
    const int total = S * (NH + NKV) * 8;
    if (id >= total) return;

    const int p4   = id & 7;                  // float4 group within 32 pairs
    const int head = (id >> 3) % (NH + NKV);  // 0..71
    const int s    = id / (8 * (NH + NKV));

    const int col = (head < NH) ? head * HD : NH * HD + (head - NH) * HD;
    float* base = qkv + (size_t)s * QKV_N + col;

    const float4 x1 = *(const float4*)(base + p4 * 4);
    const float4 x2 = *(const float4*)(base + 32 + p4 * 4);
    const float4 c  = *(const float4*)(tab + s * 64 + p4 * 4);
    const float4 sn = *(const float4*)(tab + s * 64 + 32 + p4 * 4);

    *(float4*)(base + p4 * 4) =
        make_float4(x1.x * c.x - x2.x * sn.x, x1.y * c.y - x2.y * sn.y,
                    x1.z * c.z - x2.z * sn.z, x1.w * c.w - x2.w * sn.w);
    *(float4*)(base + 32 + p4 * 4) =
        make_float4(x2.x * c.x + x1.x * sn.x, x2.y * c.y + x1.y * sn.y,
                    x2.z * c.z + x1.z * sn.z, x2.w * c.w + x1.w * sn.w);
}

// ---------------------------------------------------------------------------
// Flash attention with sink + causal mask, tf32 mma.sync.
// grid = (16 query tiles, 64 heads), 128 threads (4 warps).
// Warp w owns query rows 16w..16w+15 of the 64-row tile.
// Per ktile: S = Q K^T via m16n8k8 (Q frags in regs, scale folded in),
// register online softmax, P -> smem (aliases K buffer), O += P V via mma.
// smem row stride 68 floats -> conflict-free fragment LDS.
// ---------------------------------------------------------------------------
static constexpr int AST = 68;   // attention smem row stride (floats)

#define MMA_TF32(acc, a, b0, b1)                                            \
    asm volatile(                                                           \
        "mma.sync.aligned.m16n8k8.row.col.f32.tf32.tf32.f32 "               \
        "{%0,%1,%2,%3}, {%4,%5,%6,%7}, {%8,%9}, {%0,%1,%2,%3};"             \
        : "+f"((acc)[0]), "+f"((acc)[1]), "+f"((acc)[2]), "+f"((acc)[3])    \
        : "r"((a)[0]), "r"((a)[1]), "r"((a)[2]), "r"((a)[3]),               \
          "r"(b0), "r"(b1))

__global__ __launch_bounds__(128, 3) void attn_mma(
    const float* __restrict__ qkv, const float* __restrict__ sinks,
    float* __restrict__ obuf)
{
    __shared__ float Ks[64 * AST];   // Q staging -> K tile -> P tile
    __shared__ float Vs[64 * AST];

    const int t    = threadIdx.x;
    const int lane = t & 31;
    const int w    = t >> 5;         // warp 0..3
    const int gr   = lane >> 2;      // 0..7
    const int kc   = lane & 3;       // 0..3
    const int qt   = blockIdx.x;
    const int h    = blockIdx.y;
    const int kvh  = h >> 3;
    const int q0   = qt << 6;
    const int r0   = 16 * w + gr;    // local query row (and r0+8)

    const int qcol = h << 6;
    const int kcol = NH * HD + (kvh << 6);
    const int vcol = NH * HD + NKV * HD + (kvh << 6);

    // Stage Q tile into Ks, extract per-warp Q fragments (scale folded in)
#pragma unroll
    for (int i = 0; i < 8; ++i) {
        const int ch  = t + 128 * i;
        const int row = ch >> 4;
        const int c4  = ch & 15;
        *(float4*)(Ks + row * AST + c4 * 4) =
            *(const float4*)(qkv + (size_t)(q0 + row) * QKV_N + qcol + c4 * 4);
    }
    __syncthreads();

    uint32_t qf[8][4];
#pragma unroll
    for (int kk = 0; kk < 8; ++kk) {
        const int kb = kk * 8;
        qf[kk][0] = f2tf32(Ks[r0 * AST + kb + kc] * 0.125f);
        qf[kk][1] = f2tf32(Ks[(r0 + 8) * AST + kb + kc] * 0.125f);
        qf[kk][2] = f2tf32(Ks[r0 * AST + kb + kc + 4] * 0.125f);
        qf[kk][3] = f2tf32(Ks[(r0 + 8) * AST + kb + kc + 4] * 0.125f);
    }

    float m0 = -1e30f, m1 = -1e30f, l0 = 0.f, l1 = 0.f;
    float oacc[8][4];
#pragma unroll
    for (int j = 0; j < 8; ++j)
#pragma unroll
        for (int r = 0; r < 4; ++r) oacc[j][r] = 0.f;

    for (int kt = 0; kt <= qt; ++kt) {
        const int k0 = kt << 6;

        __syncthreads();   // prior P/V reads complete
#pragma unroll
        for (int i = 0; i < 8; ++i) {
            const int ch  = t + 128 * i;
            const int row = ch >> 4;
            const int c4  = ch & 15;
            const float* src = qkv + (size_t)(k0 + row) * QKV_N;
            *(float4*)(Ks + row * AST + c4 * 4) = *(const float4*)(src + kcol + c4 * 4);
            *(float4*)(Vs + row * AST + c4 * 4) = *(const float4*)(src + vcol + c4 * 4);
        }
        __syncthreads();

        // Scores: S = Q K^T (warp: 16 rows x 64 keys)
        float sacc[8][4];
#pragma unroll
        for (int j = 0; j < 8; ++j)
#pragma unroll
            for (int r = 0; r < 4; ++r) sacc[j][r] = 0.f;

#pragma unroll
        for (int kk = 0; kk < 8; ++kk) {
            const int kb = kk * 8;
            uint32_t bf[8][2];
#pragma unroll
            for (int j = 0; j < 8; ++j) {
                bf[j][0] = f2tf32(Ks[(j * 8 + gr) * AST + kb + kc]);
                bf[j][1] = f2tf32(Ks[(j * 8 + gr) * AST + kb + kc + 4]);
            }
#pragma unroll
            for (int j = 0; j < 8; ++j)
                MMA_TF32(sacc[j], qf[kk], bf[j][0], bf[j][1]);
        }

        // Causal mask (diagonal tile only; local row/col comparison valid)
        if (kt == qt) {
#pragma unroll
            for (int j = 0; j < 8; ++j) {
                const int c = j * 8 + kc * 2;
                if (c     > r0)     sacc[j][0] = -1e30f;
                if (c + 1 > r0)     sacc[j][1] = -1e30f;
                if (c     > r0 + 8) sacc[j][2] = -1e30f;
                if (c + 1 > r0 + 8) sacc[j][3] = -1e30f;
            }
        }

        // Online softmax (rows r0, r0+8 live in 4-lane groups)
        float mx0 = -1e30f, mx1 = -1e30f;
#pragma unroll
        for (int j = 0; j < 8; ++j) {
            mx0 = fmaxf(mx0, fmaxf(sacc[j][0], sacc[j][1]));
            mx1 = fmaxf(mx1, fmaxf(sacc[j][2], sacc[j][3]));
        }
        mx0 = fmaxf(mx0, __shfl_xor_sync(0xffffffffu, mx0, 1));
        mx0 = fmaxf(mx0, __shfl_xor_sync(0xffffffffu, mx0, 2));
        mx1 = fmaxf(mx1, __shfl_xor_sync(0xffffffffu, mx1, 1));
        mx1 = fmaxf(mx1, __shfl_xor_sync(0xffffffffu, mx1, 2));

        const float mn0 = fmaxf(m0, mx0);
        const float mn1 = fmaxf(m1, mx1);
        const float cs0 = __expf(m0 - mn0);
        const float cs1 = __expf(m1 - mn1);
        float sum0 = 0.f, sum1 = 0.f;
#pragma unroll
        for (int j = 0; j < 8; ++j) {
            sacc[j][0] = __expf(sacc[j][0] - mn0);
            sacc[j][1] = __expf(sacc[j][1] - mn0);
            sacc[j][2] = __expf(sacc[j][2] - mn1);
            sacc[j][3] = __expf(sacc[j][3] - mn1);
            sum0 += sacc[j][0] + sacc[j][1];
            sum1 += sacc[j][2] + sacc[j][3];
        }
        sum0 += __shfl_xor_sync(0xffffffffu, sum0, 1);
        sum0 += __shfl_xor_sync(0xffffffffu, sum0, 2);
        sum1 += __shfl_xor_sync(0xffffffffu, sum1, 1);
        sum1 += __shfl_xor_sync(0xffffffffu, sum1, 2);
        l0 = l0 * cs0 + sum0;  m0 = mn0;
        l1 = l1 * cs1 + sum1;  m1 = mn1;
#pragma unroll
        for (int j = 0; j < 8; ++j) {
            oacc[j][0] *= cs0; oacc[j][1] *= cs0;
            oacc[j][2] *= cs1; oacc[j][3] *= cs1;
        }

        __syncthreads();   // all warps finished reading K fragments
        // Write P (tf32-rounded) into Ks; warp-private rows after this point
#pragma unroll
        for (int j = 0; j < 8; ++j) {
            const int c = j * 8 + kc * 2;
            uint32_t* p0 = (uint32_t*)(Ks + r0 * AST + c);
            uint32_t* p1 = (uint32_t*)(Ks + (r0 + 8) * AST + c);
            p0[0] = f2tf32(sacc[j][0]); p0[1] = f2tf32(sacc[j][1]);
            p1[0] = f2tf32(sacc[j][2]); p1[1] = f2tf32(sacc[j][3]);
        }
        __syncwarp();

        // O += P V
#pragma unroll
        for (int kk = 0; kk < 8; ++kk) {
            const int kb = kk * 8;
            uint32_t af[4];
            af[0] = *(const uint32_t*)(Ks + r0 * AST + kb + kc);
            af[1] = *(const uint32_t*)(Ks + (r0 + 8) * AST + kb + kc);
            af[2] = *(const uint32_t*)(Ks + r0 * AST + kb + kc + 4);
            af[3] = *(const uint32_t*)(Ks + (r0 + 8) * AST + kb + kc + 4);
#pragma unroll
            for (int j = 0; j < 8; ++j) {
                const uint32_t b0 = f2tf32(Vs[(kb + kc) * AST + j * 8 + gr]);
                const uint32_t b1 = f2tf32(Vs[(kb + kc + 4) * AST + j * 8 + gr]);
                MMA_TF32(oacc[j], af, b0, b1);
            }
        }
    }

    // Epilogue: fold sink into denominator, normalize, store
    const float snk = sinks[h];
    const float mf0 = fmaxf(m0, snk);
    const float mf1 = fmaxf(m1, snk);
    const float c0  = __expf(m0 - mf0);
    const float c1  = __expf(m1 - mf1);
    const float inv0 = c0 / (l0 * c0 + __expf(snk - mf0));
    const float inv1 = c1 / (l1 * c1 + __expf(snk - mf1));

    const int rg = q0 + r0;
#pragma unroll
    for (int j = 0; j < 8; ++j) {
        const int col = (h << 6) + j * 8 + kc * 2;
        *(float2*)(obuf + (size_t)rg * OD + col) =
            make_float2(oacc[j][0] * inv0, oacc[j][1] * inv0);
        *(float2*)(obuf + (size_t)(rg + 8) * OD + col) =
            make_float2(oacc[j][2] * inv1, oacc[j][3] * inv1);
    }
}

// ---------------------------------------------------------------------------
extern "C" void kernel_launch(void* const* d_in, const int* in_sizes, int n_in,
                              void* d_out, int out_size)
{
    const int*   positions = (const int*)  d_in[0];
    const float* hidden    = (const float*)d_in[1];
    const float* qkv_w     = (const float*)d_in[2];
    const float* o_w       = (const float*)d_in[3];
    const float* sinks     = (const float*)d_in[4];
    float*       out       = (float*)d_out;

    void* p;
    cudaGetSymbolAddress(&p, g_qkv);
    float* qkvbuf = (float*)p;
    cudaGetSymbolAddress(&p, g_attn);
    float* attnbuf = (float*)p;
    cudaGetSymbolAddress(&p, g_rope);
    float* ropetab = (float*)p;

    // 1) QKV projection: (1024 x 2880) @ (5120 x 2880)^T -> (1024 x 5120)
    gemm_tf32<<<dim3(QKV_N / BN, S / BM), 256>>>(hidden, qkv_w, qkvbuf, S, QKV_N, H);

    // 2) RoPE: table then apply
    rope_table<<<(S * 32 + 255) / 256, 256>>>(positions, ropetab);
    {
        const int total = S * (NH + NKV) * 8;
        rope_apply<<<(total + 255) / 256, 256>>>(qkvbuf, ropetab);
    }

    // 3) Flash attention with sinks (tensor cores)
    attn_mma<<<dim3(S / 64, NH), 128>>>(qkvbuf, sinks, attnbuf);

    // 4) Output projection: (1024 x 4096) @ (2880 x 4096)^T -> (1024 x 2880)
    gemm_tf32<<<dim3((H + BN - 1) / BN, S / BM), 256>>>(attnbuf, o_w, out, S, H, OD);
}

// round 9
// speedup vs baseline: 1.4756x; 1.4756x over previous
#include <cuda_runtime.h>
#include <cstdint>
#include <math.h>

// Problem constants
static constexpr int S   = 1024;
static constexpr int H   = 2880;
static constexpr int NH  = 64;
static constexpr int NKV = 8;
static constexpr int HD  = 64;
static constexpr int QKV_N = (NH + 2 * NKV) * HD;   // 5120
static constexpr int OD    = NH * HD;               // 4096

// Scratch (allocation-free rule: __device__ globals)
__device__ __align__(16) float g_qkv [S * QKV_N];   // 20 MB
__device__ __align__(16) float g_attn[S * OD];      // 16 MB
__device__ __align__(16) float g_rope[S * 64];      // cos[32] | sin[32] per row

// ---------------------------------------------------------------------------
// TF32 tensor-core GEMM:  C[M,N] = A[M,K] @ B[N,K]^T
// 128x64 block tile, BK=16, 3-stage cp.async pipeline, 256 threads (8 warps,
// 4x2), warp tile 32x32 via m16n8k8 tf32 MMA.
// Requires: M%128==0, N%64==0, K%16==0 (all exact for this problem).
// ---------------------------------------------------------------------------
static constexpr int BM = 128, BN = 64, BK = 16, STAGES = 3;
static constexpr int SST = 20;                  // padded smem row stride (floats)

__device__ __forceinline__ uint32_t f2tf32(float f) {
    uint32_t r;
    asm volatile("cvt.rna.tf32.f32 %0, %1;" : "=r"(r) : "f"(f));
    return r;
}

__device__ __forceinline__ void cp16(float* s, const float* g) {
    uint32_t sa = (uint32_t)__cvta_generic_to_shared(s);
    asm volatile("cp.async.cg.shared.global [%0], [%1], 16;"
                 :: "r"(sa), "l"(g));
}

__global__ __launch_bounds__(256, 2) void gemm_tf32(
    const float* __restrict__ A, const float* __restrict__ B,
    float* __restrict__ C, int M, int N, int K)
{
    __shared__ float As[STAGES][BM * SST];   // 3*128*20*4 = 30720 B
    __shared__ float Bs[STAGES][BN * SST];   // 3* 64*20*4 = 15360 B

    const int t    = threadIdx.x;
    const int lane = t & 31;
    const int warp = t >> 5;
    const int wRow = warp >> 1;          // 0..3 -> 32-row slab
    const int wCol = warp & 1;           // 0..1 -> 32-col slab
    const int bm   = blockIdx.y * BM;
    const int bn   = blockIdx.x * BN;

    const int gr = lane >> 2;            // 0..7
    const int kc = lane & 3;             // 0..3

    float acc[2][4][4];
#pragma unroll
    for (int i = 0; i < 2; ++i)
#pragma unroll
        for (int j = 0; j < 4; ++j)
#pragma unroll
            for (int r = 0; r < 4; ++r) acc[i][j][r] = 0.f;

    // Loaders: A = 512 float4 chunks (2/thread), B = 256 chunks (1/thread)
    const int lrow = t >> 2;             // 0..63
    const int lc4  = (t & 3) << 2;       // 0,4,8,12
    auto load_tile = [&](int st, int kt) {
        cp16(&As[st][lrow * SST + lc4],          A + (size_t)(bm + lrow) * K + kt + lc4);
        cp16(&As[st][(lrow + 64) * SST + lc4],   A + (size_t)(bm + lrow + 64) * K + kt + lc4);
        cp16(&Bs[st][lrow * SST + lc4],          B + (size_t)(bn + lrow) * K + kt + lc4);
    };

    load_tile(0, 0);
    asm volatile("cp.async.commit_group;");
    load_tile(1, BK);
    asm volatile("cp.async.commit_group;");

    int st = 0;
    for (int kt = 0; kt < K; kt += BK) {
        asm volatile("cp.async.wait_group 1;");
        __syncthreads();

        // Prefetch stage st+2 (that buffer was consumed in iteration kt-BK;
        // everyone is past the barrier, so it is free to overwrite).
        const int pf = kt + 2 * BK;
        if (pf < K) {
            int ps = st + 2; if (ps >= STAGES) ps -= STAGES;
            load_tile(ps, pf);
        }
        asm volatile("cp.async.commit_group;");

        const float* as = As[st];
        const float* bs = Bs[st];
#pragma unroll
        for (int k8 = 0; k8 < BK; k8 += 8) {
            uint32_t af[2][4], bf[4][2];
#pragma unroll
            for (int i = 0; i < 2; ++i) {
                const int rb = wRow * 32 + i * 16;
                af[i][0] = f2tf32(as[(rb + gr)     * SST + k8 + kc]);
                af[i][1] = f2tf32(as[(rb + gr + 8) * SST + k8 + kc]);
                af[i][2] = f2tf32(as[(rb + gr)     * SST + k8 + kc + 4]);
                af[i][3] = f2tf32(as[(rb + gr + 8) * SST + k8 + kc + 4]);
            }
#pragma unroll
            for (int j = 0; j < 4; ++j) {
                const int cb = wCol * 32 + j * 8;
                bf[j][0] = f2tf32(bs[(cb + gr) * SST + k8 + kc]);
                bf[j][1] = f2tf32(bs[(cb + gr) * SST + k8 + kc + 4]);
            }
#pragma unroll
            for (int i = 0; i < 2; ++i)
#pragma unroll
                for (int j = 0; j < 4; ++j) {
                    asm volatile(
                        "mma.sync.aligned.m16n8k8.row.col.f32.tf32.tf32.f32 "
                        "{%0,%1,%2,%3}, {%4,%5,%6,%7}, {%8,%9}, {%0,%1,%2,%3};"
                        : "+f"(acc[i][j][0]), "+f"(acc[i][j][1]),
                          "+f"(acc[i][j][2]), "+f"(acc[i][j][3])
                        : "r"(af[i][0]), "r"(af[i][1]), "r"(af[i][2]), "r"(af[i][3]),
                          "r"(bf[j][0]), "r"(bf[j][1]));
                }
        }
        __syncthreads();
        if (++st == STAGES) st = 0;
    }

    // Epilogue (no guards: N % 64 == 0)
#pragma unroll
    for (int i = 0; i < 2; ++i) {
        const int row = bm + wRow * 32 + i * 16 + gr;
#pragma unroll
        for (int j = 0; j < 4; ++j) {
            const int col = bn + wCol * 32 + j * 8 + kc * 2;
            *(float2*)(C + (size_t)row * N + col) =
                make_float2(acc[i][j][0], acc[i][j][1]);
            *(float2*)(C + (size_t)(row + 8) * N + col) =
                make_float2(acc[i][j][2], acc[i][j][3]);
        }
    }
}

// ---------------------------------------------------------------------------
// RoPE: precompute cos/sin table (double sincos), then vectorized apply.
// ---------------------------------------------------------------------------
__global__ void rope_table(const int* __restrict__ positions, float* __restrict__ tab)
{
    const int id = blockIdx.x * blockDim.x + threadIdx.x;
    if (id >= S * 32) return;
    const int p = id & 31;
    const int s = id >> 5;
    const float freq = 1.0f / powf(10000.0f, (float)p * (1.0f / 32.0f));
    const float ang  = (float)positions[s] * freq;
    double sd, cd;
    sincos((double)ang, &sd, &cd);
    tab[s * 64 + p]      = (float)cd;
    tab[s * 64 + 32 + p] = (float)sd;
}

__global__ void rope_apply(float* __restrict__ qkv, const float* __restrict__ tab)
{
    const int id = blockIdx.x * blockDim.x + threadIdx.x;
    const int total = S * (NH + NKV) * 8;
    if (id >= total) return;

    const int p4   = id & 7;
    const int head = (id >> 3) % (NH + NKV);
    const int s    = id / (8 * (NH + NKV));

    const int col = (head < NH) ? head * HD : NH * HD + (head - NH) * HD;
    float* base = qkv + (size_t)s * QKV_N + col;

    const float4 x1 = *(const float4*)(base + p4 * 4);
    const float4 x2 = *(const float4*)(base + 32 + p4 * 4);
    const float4 c  = *(const float4*)(tab + s * 64 + p4 * 4);
    const float4 sn = *(const float4*)(tab + s * 64 + 32 + p4 * 4);

    *(float4*)(base + p4 * 4) =
        make_float4(x1.x * c.x - x2.x * sn.x, x1.y * c.y - x2.y * sn.y,
                    x1.z * c.z - x2.z * sn.z, x1.w * c.w - x2.w * sn.w);
    *(float4*)(base + 32 + p4 * 4) =
        make_float4(x2.x * c.x + x1.x * sn.x, x2.y * c.y + x1.y * sn.y,
                    x2.z * c.z + x1.z * sn.z, x2.w * c.w + x1.w * sn.w);
}

// ---------------------------------------------------------------------------
// Flash attention with sink + causal mask, tf32 mma.sync (unchanged from R5).
// ---------------------------------------------------------------------------
static constexpr int AST = 68;   // attention smem row stride (floats)

#define MMA_TF32(acc, a, b0, b1)                                            \
    asm volatile(                                                           \
        "mma.sync.aligned.m16n8k8.row.col.f32.tf32.tf32.f32 "               \
        "{%0,%1,%2,%3}, {%4,%5,%6,%7}, {%8,%9}, {%0,%1,%2,%3};"             \
        : "+f"((acc)[0]), "+f"((acc)[1]), "+f"((acc)[2]), "+f"((acc)[3])    \
        : "r"((a)[0]), "r"((a)[1]), "r"((a)[2]), "r"((a)[3]),               \
          "r"(b0), "r"(b1))

__global__ __launch_bounds__(128, 3) void attn_mma(
    const float* __restrict__ qkv, const float* __restrict__ sinks,
    float* __restrict__ obuf)
{
    __shared__ float Ks[64 * AST];   // Q staging -> K tile -> P tile
    __shared__ float Vs[64 * AST];

    const int t    = threadIdx.x;
    const int lane = t & 31;
    const int w    = t >> 5;
    const int gr   = lane >> 2;
    const int kc   = lane & 3;
    const int qt   = blockIdx.x;
    const int h    = blockIdx.y;
    const int kvh  = h >> 3;
    const int q0   = qt << 6;
    const int r0   = 16 * w + gr;

    const int qcol = h << 6;
    const int kcol = NH * HD + (kvh << 6);
    const int vcol = NH * HD + NKV * HD + (kvh << 6);

#pragma unroll
    for (int i = 0; i < 8; ++i) {
        const int ch  = t + 128 * i;
        const int row = ch >> 4;
        const int c4  = ch & 15;
        *(float4*)(Ks + row * AST + c4 * 4) =
            *(const float4*)(qkv + (size_t)(q0 + row) * QKV_N + qcol + c4 * 4);
    }
    __syncthreads();

    uint32_t qf[8][4];
#pragma unroll
    for (int kk = 0; kk < 8; ++kk) {
        const int kb = kk * 8;
        qf[kk][0] = f2tf32(Ks[r0 * AST + kb + kc] * 0.125f);
        qf[kk][1] = f2tf32(Ks[(r0 + 8) * AST + kb + kc] * 0.125f);
        qf[kk][2] = f2tf32(Ks[r0 * AST + kb + kc + 4] * 0.125f);
        qf[kk][3] = f2tf32(Ks[(r0 + 8) * AST + kb + kc + 4] * 0.125f);
    }

    float m0 = -1e30f, m1 = -1e30f, l0 = 0.f, l1 = 0.f;
    float oacc[8][4];
#pragma unroll
    for (int j = 0; j < 8; ++j)
#pragma unroll
        for (int r = 0; r < 4; ++r) oacc[j][r] = 0.f;

    for (int kt = 0; kt <= qt; ++kt) {
        const int k0 = kt << 6;

        __syncthreads();
#pragma unroll
        for (int i = 0; i < 8; ++i) {
            const int ch  = t + 128 * i;
            const int row = ch >> 4;
            const int c4  = ch & 15;
            const float* src = qkv + (size_t)(k0 + row) * QKV_N;
            *(float4*)(Ks + row * AST + c4 * 4) = *(const float4*)(src + kcol + c4 * 4);
            *(float4*)(Vs + row * AST + c4 * 4) = *(const float4*)(src + vcol + c4 * 4);
        }
        __syncthreads();

        float sacc[8][4];
#pragma unroll
        for (int j = 0; j < 8; ++j)
#pragma unroll
            for (int r = 0; r < 4; ++r) sacc[j][r] = 0.f;

#pragma unroll
        for (int kk = 0; kk < 8; ++kk) {
            const int kb = kk * 8;
            uint32_t bf[8][2];
#pragma unroll
            for (int j = 0; j < 8; ++j) {
                bf[j][0] = f2tf32(Ks[(j * 8 + gr) * AST + kb + kc]);
                bf[j][1] = f2tf32(Ks[(j * 8 + gr) * AST + kb + kc + 4]);
            }
#pragma unroll
            for (int j = 0; j < 8; ++j)
                MMA_TF32(sacc[j], qf[kk], bf[j][0], bf[j][1]);
        }

        if (kt == qt) {
#pragma unroll
            for (int j = 0; j < 8; ++j) {
                const int c = j * 8 + kc * 2;
                if (c     > r0)     sacc[j][0] = -1e30f;
                if (c + 1 > r0)     sacc[j][1] = -1e30f;
                if (c     > r0 + 8) sacc[j][2] = -1e30f;
                if (c + 1 > r0 + 8) sacc[j][3] = -1e30f;
            }
        }

        float mx0 = -1e30f, mx1 = -1e30f;
#pragma unroll
        for (int j = 0; j < 8; ++j) {
            mx0 = fmaxf(mx0, fmaxf(sacc[j][0], sacc[j][1]));
            mx1 = fmaxf(mx1, fmaxf(sacc[j][2], sacc[j][3]));
        }
        mx0 = fmaxf(mx0, __shfl_xor_sync(0xffffffffu, mx0, 1));
        mx0 = fmaxf(mx0, __shfl_xor_sync(0xffffffffu, mx0, 2));
        mx1 = fmaxf(mx1, __shfl_xor_sync(0xffffffffu, mx1, 1));
        mx1 = fmaxf(mx1, __shfl_xor_sync(0xffffffffu, mx1, 2));

        const float mn0 = fmaxf(m0, mx0);
        const float mn1 = fmaxf(m1, mx1);
        const float cs0 = __expf(m0 - mn0);
        const float cs1 = __expf(m1 - mn1);
        float sum0 = 0.f, sum1 = 0.f;
#pragma unroll
        for (int j = 0; j < 8; ++j) {
            sacc[j][0] = __expf(sacc[j][0] - mn0);
            sacc[j][1] = __expf(sacc[j][1] - mn0);
            sacc[j][2] = __expf(sacc[j][2] - mn1);
            sacc[j][3] = __expf(sacc[j][3] - mn1);
            sum0 += sacc[j][0] + sacc[j][1];
            sum1 += sacc[j][2] + sacc[j][3];
        }
        sum0 += __shfl_xor_sync(0xffffffffu, sum0, 1);
        sum0 += __shfl_xor_sync(0xffffffffu, sum0, 2);
        sum1 += __shfl_xor_sync(0xffffffffu, sum1, 1);
        sum1 += __shfl_xor_sync(0xffffffffu, sum1, 2);
        l0 = l0 * cs0 + sum0;  m0 = mn0;
        l1 = l1 * cs1 + sum1;  m1 = mn1;
#pragma unroll
        for (int j = 0; j < 8; ++j) {
            oacc[j][0] *= cs0; oacc[j][1] *= cs0;
            oacc[j][2] *= cs1; oacc[j][3] *= cs1;
        }

        __syncthreads();
#pragma unroll
        for (int j = 0; j < 8; ++j) {
            const int c = j * 8 + kc * 2;
            uint32_t* p0 = (uint32_t*)(Ks + r0 * AST + c);
            uint32_t* p1 = (uint32_t*)(Ks + (r0 + 8) * AST + c);
            p0[0] = f2tf32(sacc[j][0]); p0[1] = f2tf32(sacc[j][1]);
            p1[0] = f2tf32(sacc[j][2]); p1[1] = f2tf32(sacc[j][3]);
        }
        __syncwarp();

#pragma unroll
        for (int kk = 0; kk < 8; ++kk) {
            const int kb = kk * 8;
            uint32_t af[4];
            af[0] = *(const uint32_t*)(Ks + r0 * AST + kb + kc);
            af[1] = *(const uint32_t*)(Ks + (r0 + 8) * AST + kb + kc);
            af[2] = *(const uint32_t*)(Ks + r0 * AST + kb + kc + 4);
            af[3] = *(const uint32_t*)(Ks + (r0 + 8) * AST + kb + kc + 4);
#pragma unroll
            for (int j = 0; j < 8; ++j) {
                const uint32_t b0 = f2tf32(Vs[(kb + kc) * AST + j * 8 + gr]);
                const uint32_t b1 = f2tf32(Vs[(kb + kc + 4) * AST + j * 8 + gr]);
                MMA_TF32(oacc[j], af, b0, b1);
            }
        }
    }

    const float snk = sinks[h];
    const float mf0 = fmaxf(m0, snk);
    const float mf1 = fmaxf(m1, snk);
    const float c0  = __expf(m0 - mf0);
    const float c1  = __expf(m1 - mf1);
    const float inv0 = c0 / (l0 * c0 + __expf(snk - mf0));
    const float inv1 = c1 / (l1 * c1 + __expf(snk - mf1));

    const int rg = q0 + r0;
#pragma unroll
    for (int j = 0; j < 8; ++j) {
        const int col = (h << 6) + j * 8 + kc * 2;
        *(float2*)(obuf + (size_t)rg * OD + col) =
            make_float2(oacc[j][0] * inv0, oacc[j][1] * inv0);
        *(float2*)(obuf + (size_t)(rg + 8) * OD + col) =
            make_float2(oacc[j][2] * inv1, oacc[j][3] * inv1);
    }
}

// ---------------------------------------------------------------------------
extern "C" void kernel_launch(void* const* d_in, const int* in_sizes, int n_in,
                              void* d_out, int out_size)
{
    const int*   positions = (const int*)  d_in[0];
    const float* hidden    = (const float*)d_in[1];
    const float* qkv_w     = (const float*)d_in[2];
    const float* o_w       = (const float*)d_in[3];
    const float* sinks     = (const float*)d_in[4];
    float*       out       = (float*)d_out;

    void* p;
    cudaGetSymbolAddress(&p, g_qkv);
    float* qkvbuf = (float*)p;
    cudaGetSymbolAddress(&p, g_attn);
    float* attnbuf = (float*)p;
    cudaGetSymbolAddress(&p, g_rope);
    float* ropetab = (float*)p;

    // 1) QKV projection: (1024 x 2880) @ (5120 x 2880)^T -> (1024 x 5120)
    gemm_tf32<<<dim3(QKV_N / BN, S / BM), 256>>>(hidden, qkv_w, qkvbuf, S, QKV_N, H);

    // 2) RoPE: table then apply
    rope_table<<<(S * 32 + 255) / 256, 256>>>(positions, ropetab);
    {
        const int total = S * (NH + NKV) * 8;
        rope_apply<<<(total + 255) / 256, 256>>>(qkvbuf, ropetab);
    }

    // 3) Flash attention with sinks (tensor cores)
    attn_mma<<<dim3(S / 64, NH), 128>>>(qkvbuf, sinks, attnbuf);

    // 4) Output projection: (1024 x 4096) @ (2880 x 4096)^T -> (1024 x 2880)
    gemm_tf32<<<dim3(H / BN, S / BM), 256>>>(attnbuf, o_w, out, S, H, OD);
}

// round 10
// speedup vs baseline: 1.5182x; 1.0289x over previous
#include <cuda_runtime.h>
#include <cstdint>
#include <math.h>

// Problem constants
static constexpr int S   = 1024;
static constexpr int H   = 2880;
static constexpr int NH  = 64;
static constexpr int NKV = 8;
static constexpr int HD  = 64;
static constexpr int QKV_N = (NH + 2 * NKV) * HD;   // 5120
static constexpr int OD    = NH * HD;               // 4096

// Scratch (allocation-free rule: __device__ globals)
__device__ __align__(16) float g_qkv [S * QKV_N];   // 20 MB
__device__ __align__(16) float g_attn[S * OD];      // 16 MB
__device__ __align__(16) float g_rope[S * 64];      // cos[32] | sin[32] per row

// ---------------------------------------------------------------------------
// TF32 tensor-core GEMM:  C[M,N] = A[M,K] @ B[N,K]^T
// 128x64 block tile, BK=16, 3-stage cp.async pipeline, 256 threads (8 warps,
// 4x2), warp tile 32x32 via m16n8k8 tf32 MMA. Target 3 CTAs/SM.
// Requires: M%128==0, N%64==0, K%16==0 (all exact for this problem).
// ---------------------------------------------------------------------------
static constexpr int BM = 128, BN = 64, BK = 16, STAGES = 3;
static constexpr int SST = 20;                  // padded smem row stride (floats)

__device__ __forceinline__ uint32_t f2tf32(float f) {
    uint32_t r;
    asm volatile("cvt.rna.tf32.f32 %0, %1;" : "=r"(r) : "f"(f));
    return r;
}

__device__ __forceinline__ void cp16(float* s, const float* g) {
    uint32_t sa = (uint32_t)__cvta_generic_to_shared(s);
    asm volatile("cp.async.cg.shared.global [%0], [%1], 16;"
                 :: "r"(sa), "l"(g));
}

__global__ __launch_bounds__(256, 3) void gemm_tf32(
    const float* __restrict__ A, const float* __restrict__ B,
    float* __restrict__ C, int M, int N, int K)
{
    __shared__ float As[STAGES][BM * SST];   // 30720 B
    __shared__ float Bs[STAGES][BN * SST];   // 15360 B

    const int t    = threadIdx.x;
    const int lane = t & 31;
    const int warp = t >> 5;
    const int wRow = warp >> 1;          // 0..3 -> 32-row slab
    const int wCol = warp & 1;           // 0..1 -> 32-col slab
    const int bm   = blockIdx.y * BM;
    const int bn   = blockIdx.x * BN;

    const int gr = lane >> 2;            // 0..7
    const int kc = lane & 3;             // 0..3

    float acc[2][4][4];
#pragma unroll
    for (int i = 0; i < 2; ++i)
#pragma unroll
        for (int j = 0; j < 4; ++j)
#pragma unroll
            for (int r = 0; r < 4; ++r) acc[i][j][r] = 0.f;

    const int lrow = t >> 2;             // 0..63
    const int lc4  = (t & 3) << 2;       // 0,4,8,12
    auto load_tile = [&](int st, int kt) {
        cp16(&As[st][lrow * SST + lc4],          A + (size_t)(bm + lrow) * K + kt + lc4);
        cp16(&As[st][(lrow + 64) * SST + lc4],   A + (size_t)(bm + lrow + 64) * K + kt + lc4);
        cp16(&Bs[st][lrow * SST + lc4],          B + (size_t)(bn + lrow) * K + kt + lc4);
    };

    load_tile(0, 0);
    asm volatile("cp.async.commit_group;");
    load_tile(1, BK);
    asm volatile("cp.async.commit_group;");

    int st = 0;
    for (int kt = 0; kt < K; kt += BK) {
        asm volatile("cp.async.wait_group 1;");
        __syncthreads();

        const int pf = kt + 2 * BK;
        if (pf < K) {
            int ps = st + 2; if (ps >= STAGES) ps -= STAGES;
            load_tile(ps, pf);
        }
        asm volatile("cp.async.commit_group;");

        const float* as = As[st];
        const float* bs = Bs[st];
#pragma unroll
        for (int k8 = 0; k8 < BK; k8 += 8) {
            uint32_t af[2][4], bf[4][2];
#pragma unroll
            for (int i = 0; i < 2; ++i) {
                const int rb = wRow * 32 + i * 16;
                af[i][0] = f2tf32(as[(rb + gr)     * SST + k8 + kc]);
                af[i][1] = f2tf32(as[(rb + gr + 8) * SST + k8 + kc]);
                af[i][2] = f2tf32(as[(rb + gr)     * SST + k8 + kc + 4]);
                af[i][3] = f2tf32(as[(rb + gr + 8) * SST + k8 + kc + 4]);
            }
#pragma unroll
            for (int j = 0; j < 4; ++j) {
                const int cb = wCol * 32 + j * 8;
                bf[j][0] = f2tf32(bs[(cb + gr) * SST + k8 + kc]);
                bf[j][1] = f2tf32(bs[(cb + gr) * SST + k8 + kc + 4]);
            }
#pragma unroll
            for (int i = 0; i < 2; ++i)
#pragma unroll
                for (int j = 0; j < 4; ++j) {
                    asm volatile(
                        "mma.sync.aligned.m16n8k8.row.col.f32.tf32.tf32.f32 "
                        "{%0,%1,%2,%3}, {%4,%5,%6,%7}, {%8,%9}, {%0,%1,%2,%3};"
                        : "+f"(acc[i][j][0]), "+f"(acc[i][j][1]),
                          "+f"(acc[i][j][2]), "+f"(acc[i][j][3])
                        : "r"(af[i][0]), "r"(af[i][1]), "r"(af[i][2]), "r"(af[i][3]),
                          "r"(bf[j][0]), "r"(bf[j][1]));
                }
        }
        __syncthreads();
        if (++st == STAGES) st = 0;
    }

#pragma unroll
    for (int i = 0; i < 2; ++i) {
        const int row = bm + wRow * 32 + i * 16 + gr;
#pragma unroll
        for (int j = 0; j < 4; ++j) {
            const int col = bn + wCol * 32 + j * 8 + kc * 2;
            *(float2*)(C + (size_t)row * N + col) =
                make_float2(acc[i][j][0], acc[i][j][1]);
            *(float2*)(C + (size_t)(row + 8) * N + col) =
                make_float2(acc[i][j][2], acc[i][j][3]);
        }
    }
}

// ---------------------------------------------------------------------------
// RoPE cos/sin table (double sincos). Apply is fused into attention.
// ---------------------------------------------------------------------------
__global__ void rope_table(const int* __restrict__ positions, float* __restrict__ tab)
{
    const int id = blockIdx.x * blockDim.x + threadIdx.x;
    if (id >= S * 32) return;
    const int p = id & 31;
    const int s = id >> 5;
    const float freq = 1.0f / powf(10000.0f, (float)p * (1.0f / 32.0f));
    const float ang  = (float)positions[s] * freq;
    double sd, cd;
    sincos((double)ang, &sd, &cd);
    tab[s * 64 + p]      = (float)cd;
    tab[s * 64 + 32 + p] = (float)sd;
}

// ---------------------------------------------------------------------------
// Flash attention with sink + causal mask, tf32 mma.sync.
// RoPE applied inline on Q/K loads (fp32, then tf32 round — same numerics as
// the separate-pass version). K and V are stored in smem ALREADY tf32-rounded
// so the hot MMA loops do raw LDS with zero cvt.
// ---------------------------------------------------------------------------
static constexpr int AST = 68;   // attention smem row stride (floats)

#define MMA_TF32(acc, a, b0, b1)                                            \
    asm volatile(                                                           \
        "mma.sync.aligned.m16n8k8.row.col.f32.tf32.tf32.f32 "               \
        "{%0,%1,%2,%3}, {%4,%5,%6,%7}, {%8,%9}, {%0,%1,%2,%3};"             \
        : "+f"((acc)[0]), "+f"((acc)[1]), "+f"((acc)[2]), "+f"((acc)[3])    \
        : "r"((a)[0]), "r"((a)[1]), "r"((a)[2]), "r"((a)[3]),               \
          "r"(b0), "r"(b1))

__global__ __launch_bounds__(128, 3) void attn_mma(
    const float* __restrict__ qkv, const float* __restrict__ sinks,
    const float* __restrict__ tab, float* __restrict__ obuf)
{
    __shared__ float Ks[64 * AST];   // Q staging -> K tile (tf32 bits) -> P tile
    __shared__ float Vs[64 * AST];   // V tile (tf32 bits)

    const int t    = threadIdx.x;
    const int lane = t & 31;
    const int w    = t >> 5;
    const int gr   = lane >> 2;
    const int kc   = lane & 3;
    const int qt   = blockIdx.x;
    const int h    = blockIdx.y;
    const int kvh  = h >> 3;
    const int q0   = qt << 6;
    const int r0   = 16 * w + gr;

    const int qcol = h << 6;
    const int kcol = NH * HD + (kvh << 6);
    const int vcol = NH * HD + NKV * HD + (kvh << 6);

    // Stage Q tile with inline RoPE (fp32 values in Ks)
#pragma unroll
    for (int i = 0; i < 4; ++i) {
        const int task = t + 128 * i;       // 0..511
        const int row  = task >> 3;         // 0..63
        const int p4   = (task & 7) << 2;   // 0,4,...,28
        const float* src = qkv + (size_t)(q0 + row) * QKV_N + qcol;
        const float* tb  = tab + (size_t)(q0 + row) * 64;
        const float4 x1 = *(const float4*)(src + p4);
        const float4 x2 = *(const float4*)(src + 32 + p4);
        const float4 c  = *(const float4*)(tb + p4);
        const float4 sn = *(const float4*)(tb + 32 + p4);
        *(float4*)(Ks + row * AST + p4) =
            make_float4(x1.x * c.x - x2.x * sn.x, x1.y * c.y - x2.y * sn.y,
                        x1.z * c.z - x2.z * sn.z, x1.w * c.w - x2.w * sn.w);
        *(float4*)(Ks + row * AST + 32 + p4) =
            make_float4(x2.x * c.x + x1.x * sn.x, x2.y * c.y + x1.y * sn.y,
                        x2.z * c.z + x1.z * sn.z, x2.w * c.w + x1.w * sn.w);
    }
    __syncthreads();

    uint32_t qf[8][4];
#pragma unroll
    for (int kk = 0; kk < 8; ++kk) {
        const int kb = kk * 8;
        qf[kk][0] = f2tf32(Ks[r0 * AST + kb + kc] * 0.125f);
        qf[kk][1] = f2tf32(Ks[(r0 + 8) * AST + kb + kc] * 0.125f);
        qf[kk][2] = f2tf32(Ks[r0 * AST + kb + kc + 4] * 0.125f);
        qf[kk][3] = f2tf32(Ks[(r0 + 8) * AST + kb + kc + 4] * 0.125f);
    }

    float m0 = -1e30f, m1 = -1e30f, l0 = 0.f, l1 = 0.f;
    float oacc[8][4];
#pragma unroll
    for (int j = 0; j < 8; ++j)
#pragma unroll
        for (int r = 0; r < 4; ++r) oacc[j][r] = 0.f;

    for (int kt = 0; kt <= qt; ++kt) {
        const int k0 = kt << 6;

        __syncthreads();   // prior P/V reads complete, Q frags extracted
        // K tile: inline RoPE, store tf32 bits
#pragma unroll
        for (int i = 0; i < 4; ++i) {
            const int task = t + 128 * i;
            const int row  = task >> 3;
            const int p4   = (task & 7) << 2;
            const float* src = qkv + (size_t)(k0 + row) * QKV_N + kcol;
            const float* tb  = tab + (size_t)(k0 + row) * 64;
            const float4 x1 = *(const float4*)(src + p4);
            const float4 x2 = *(const float4*)(src + 32 + p4);
            const float4 c  = *(const float4*)(tb + p4);
            const float4 sn = *(const float4*)(tb + 32 + p4);
            uint4 y1, y2;
            y1.x = f2tf32(x1.x * c.x - x2.x * sn.x);
            y1.y = f2tf32(x1.y * c.y - x2.y * sn.y);
            y1.z = f2tf32(x1.z * c.z - x2.z * sn.z);
            y1.w = f2tf32(x1.w * c.w - x2.w * sn.w);
            y2.x = f2tf32(x2.x * c.x + x1.x * sn.x);
            y2.y = f2tf32(x2.y * c.y + x1.y * sn.y);
            y2.z = f2tf32(x2.z * c.z + x1.z * sn.z);
            y2.w = f2tf32(x2.w * c.w + x1.w * sn.w);
            *(uint4*)(Ks + row * AST + p4)      = y1;
            *(uint4*)(Ks + row * AST + 32 + p4) = y2;
        }
        // V tile: store tf32 bits
#pragma unroll
        for (int i = 0; i < 8; ++i) {
            const int ch  = t + 128 * i;
            const int row = ch >> 4;
            const int c4  = (ch & 15) << 2;
            const float4 v = *(const float4*)(qkv + (size_t)(k0 + row) * QKV_N + vcol + c4);
            uint4 y;
            y.x = f2tf32(v.x); y.y = f2tf32(v.y);
            y.z = f2tf32(v.z); y.w = f2tf32(v.w);
            *(uint4*)(Vs + row * AST + c4) = y;
        }
        __syncthreads();

        // Scores: S = Q K^T (raw LDS, no cvt)
        float sacc[8][4];
#pragma unroll
        for (int j = 0; j < 8; ++j)
#pragma unroll
            for (int r = 0; r < 4; ++r) sacc[j][r] = 0.f;

#pragma unroll
        for (int kk = 0; kk < 8; ++kk) {
            const int kb = kk * 8;
            uint32_t bf[8][2];
#pragma unroll
            for (int j = 0; j < 8; ++j) {
                bf[j][0] = *(const uint32_t*)(Ks + (j * 8 + gr) * AST + kb + kc);
                bf[j][1] = *(const uint32_t*)(Ks + (j * 8 + gr) * AST + kb + kc + 4);
            }
#pragma unroll
            for (int j = 0; j < 8; ++j)
                MMA_TF32(sacc[j], qf[kk], bf[j][0], bf[j][1]);
        }

        if (kt == qt) {
#pragma unroll
            for (int j = 0; j < 8; ++j) {
                const int c = j * 8 + kc * 2;
                if (c     > r0)     sacc[j][0] = -1e30f;
                if (c + 1 > r0)     sacc[j][1] = -1e30f;
                if (c     > r0 + 8) sacc[j][2] = -1e30f;
                if (c + 1 > r0 + 8) sacc[j][3] = -1e30f;
            }
        }

        float mx0 = -1e30f, mx1 = -1e30f;
#pragma unroll
        for (int j = 0; j < 8; ++j) {
            mx0 = fmaxf(mx0, fmaxf(sacc[j][0], sacc[j][1]));
            mx1 = fmaxf(mx1, fmaxf(sacc[j][2], sacc[j][3]));
        }
        mx0 = fmaxf(mx0, __shfl_xor_sync(0xffffffffu, mx0, 1));
        mx0 = fmaxf(mx0, __shfl_xor_sync(0xffffffffu, mx0, 2));
        mx1 = fmaxf(mx1, __shfl_xor_sync(0xffffffffu, mx1, 1));
        mx1 = fmaxf(mx1, __shfl_xor_sync(0xffffffffu, mx1, 2));

        const float mn0 = fmaxf(m0, mx0);
        const float mn1 = fmaxf(m1, mx1);
        const float cs0 = __expf(m0 - mn0);
        const float cs1 = __expf(m1 - mn1);
        float sum0 = 0.f, sum1 = 0.f;
#pragma unroll
        for (int j = 0; j < 8; ++j) {
            sacc[j][0] = __expf(sacc[j][0] - mn0);
            sacc[j][1] = __expf(sacc[j][1] - mn0);
            sacc[j][2] = __expf(sacc[j][2] - mn1);
            sacc[j][3] = __expf(sacc[j][3] - mn1);
            sum0 += sacc[j][0] + sacc[j][1];
            sum1 += sacc[j][2] + sacc[j][3];
        }
        sum0 += __shfl_xor_sync(0xffffffffu, sum0, 1);
        sum0 += __shfl_xor_sync(0xffffffffu, sum0, 2);
        sum1 += __shfl_xor_sync(0xffffffffu, sum1, 1);
        sum1 += __shfl_xor_sync(0xffffffffu, sum1, 2);
        l0 = l0 * cs0 + sum0;  m0 = mn0;
        l1 = l1 * cs1 + sum1;  m1 = mn1;
#pragma unroll
        for (int j = 0; j < 8; ++j) {
            oacc[j][0] *= cs0; oacc[j][1] *= cs0;
            oacc[j][2] *= cs1; oacc[j][3] *= cs1;
        }

        __syncthreads();   // all warps finished reading K fragments
#pragma unroll
        for (int j = 0; j < 8; ++j) {
            const int c = j * 8 + kc * 2;
            uint32_t* p0 = (uint32_t*)(Ks + r0 * AST + c);
            uint32_t* p1 = (uint32_t*)(Ks + (r0 + 8) * AST + c);
            p0[0] = f2tf32(sacc[j][0]); p0[1] = f2tf32(sacc[j][1]);
            p1[0] = f2tf32(sacc[j][2]); p1[1] = f2tf32(sacc[j][3]);
        }
        __syncwarp();

        // O += P V (raw LDS, no cvt)
#pragma unroll
        for (int kk = 0; kk < 8; ++kk) {
            const int kb = kk * 8;
            uint32_t af[4];
            af[0] = *(const uint32_t*)(Ks + r0 * AST + kb + kc);
            af[1] = *(const uint32_t*)(Ks + (r0 + 8) * AST + kb + kc);
            af[2] = *(const uint32_t*)(Ks + r0 * AST + kb + kc + 4);
            af[3] = *(const uint32_t*)(Ks + (r0 + 8) * AST + kb + kc + 4);
#pragma unroll
            for (int j = 0; j < 8; ++j) {
                const uint32_t b0 = *(const uint32_t*)(Vs + (kb + kc) * AST + j * 8 + gr);
                const uint32_t b1 = *(const uint32_t*)(Vs + (kb + kc + 4) * AST + j * 8 + gr);
                MMA_TF32(oacc[j], af, b0, b1);
            }
        }
    }

    const float snk = sinks[h];
    const float mf0 = fmaxf(m0, snk);
    const float mf1 = fmaxf(m1, snk);
    const float c0  = __expf(m0 - mf0);
    const float c1  = __expf(m1 - mf1);
    const float inv0 = c0 / (l0 * c0 + __expf(snk - mf0));
    const float inv1 = c1 / (l1 * c1 + __expf(snk - mf1));

    const int rg = q0 + r0;
#pragma unroll
    for (int j = 0; j < 8; ++j) {
        const int col = (h << 6) + j * 8 + kc * 2;
        *(float2*)(obuf + (size_t)rg * OD + col) =
            make_float2(oacc[j][0] * inv0, oacc[j][1] * inv0);
        *(float2*)(obuf + (size_t)(rg + 8) * OD + col) =
            make_float2(oacc[j][2] * inv1, oacc[j][3] * inv1);
    }
}

// ---------------------------------------------------------------------------
extern "C" void kernel_launch(void* const* d_in, const int* in_sizes, int n_in,
                              void* d_out, int out_size)
{
    const int*   positions = (const int*)  d_in[0];
    const float* hidden    = (const float*)d_in[1];
    const float* qkv_w     = (const float*)d_in[2];
    const float* o_w       = (const float*)d_in[3];
    const float* sinks     = (const float*)d_in[4];
    float*       out       = (float*)d_out;

    void* p;
    cudaGetSymbolAddress(&p, g_qkv);
    float* qkvbuf = (float*)p;
    cudaGetSymbolAddress(&p, g_attn);
    float* attnbuf = (float*)p;
    cudaGetSymbolAddress(&p, g_rope);
    float* ropetab = (float*)p;

    // 0) RoPE table (independent of GEMM output)
    rope_table<<<(S * 32 + 255) / 256, 256>>>(positions, ropetab);

    // 1) QKV projection: (1024 x 2880) @ (5120 x 2880)^T -> (1024 x 5120)
    gemm_tf32<<<dim3(QKV_N / BN, S / BM), 256>>>(hidden, qkv_w, qkvbuf, S, QKV_N, H);

    // 2) Flash attention with sinks (RoPE fused into Q/K loads)
    attn_mma<<<dim3(S / 64, NH), 128>>>(qkvbuf, sinks, ropetab, attnbuf);

    // 3) Output projection: (1024 x 4096) @ (2880 x 4096)^T -> (1024 x 2880)
    gemm_tf32<<<dim3(H / BN, S / BM), 256>>>(attnbuf, o_w, out, S, H, OD);
}